// round 1
// baseline (speedup 1.0000x reference)
#include <cuda_runtime.h>
#include <cuda_bf16.h>

// Problem constants
#define BB   4
#define SS   2048
#define DD   1024
#define HH   16
#define HD   64
#define MM   (BB*SS)          // 8192 rows

// ---------------------------------------------------------------------------
// Scratch (device globals; allocation-free)
// ---------------------------------------------------------------------------
__device__ float g_Q[MM * DD];
__device__ float g_K[MM * DD];
__device__ float g_V[MM * DD];
__device__ float g_CTX[MM * DD];

// ---------------------------------------------------------------------------
// SGEMM: C[M,N] = A[M,K] @ B[K,N] + bias[N]   (all row-major, fp32)
// 128x128 tile, BK=8, 256 threads, 8x8 microtile, double-buffered smem.
// M%128==0, N%128==0, K%8==0 assumed (true for all our shapes).
// ---------------------------------------------------------------------------
__global__ __launch_bounds__(256, 2)
void sgemm_bias_kernel(const float* __restrict__ A, const float* __restrict__ B,
                       const float* __restrict__ bias, float* __restrict__ C,
                       int M, int N, int K)
{
    __shared__ float As[2][8][128];
    __shared__ float Bs[2][8][128];

    const int tid  = threadIdx.x;
    const int warp = tid >> 5;
    const int lane = tid & 31;
    // 4x2 warp grid over the 128x128 tile; each warp 32x64; each lane 8x8
    const int wr = warp & 3;           // warp row (0..3)
    const int wc = warp >> 2;          // warp col (0..1)
    const int lr = lane & 3;           // lane row (0..3)
    const int lc = lane >> 2;          // lane col (0..7)
    const int row0 = wr * 32 + lr * 8; // thread's 8 rows start
    const int col0 = wc * 64 + lc * 8; // thread's 8 cols start

    const int m0 = blockIdx.y * 128;
    const int n0 = blockIdx.x * 128;

    // A tile loads: 128 rows x 8 k, one float4 per thread
    const int arow = tid >> 1;
    const int ak   = (tid & 1) * 4;
    // B tile loads: 8 k x 128 n, one float4 per thread
    const int brow = tid >> 5;
    const int bcol = (tid & 31) * 4;

    const float* Ag = A + (long)(m0 + arow) * K + ak;
    const float* Bg = B + (long)brow * N + n0 + bcol;

    float4 aReg = *(const float4*)Ag;
    float4 bReg = *(const float4*)Bg;

    float acc[8][8];
    #pragma unroll
    for (int i = 0; i < 8; i++)
        #pragma unroll
        for (int j = 0; j < 8; j++) acc[i][j] = 0.f;

    const int KT = K >> 3;
    int buf = 0;
    for (int kt = 0; kt < KT; kt++) {
        // store staged regs into smem (A transposed to k-major)
        As[buf][ak + 0][arow] = aReg.x;
        As[buf][ak + 1][arow] = aReg.y;
        As[buf][ak + 2][arow] = aReg.z;
        As[buf][ak + 3][arow] = aReg.w;
        *(float4*)(&Bs[buf][brow][bcol]) = bReg;
        __syncthreads();

        if (kt + 1 < KT) {
            aReg = *(const float4*)(Ag + (long)(kt + 1) * 8);
            bReg = *(const float4*)(Bg + (long)(kt + 1) * 8 * N);
        }

        #pragma unroll
        for (int k = 0; k < 8; k++) {
            float a[8], b[8];
            *(float4*)(a)     = *(const float4*)(&As[buf][k][row0]);
            *(float4*)(a + 4) = *(const float4*)(&As[buf][k][row0 + 4]);
            *(float4*)(b)     = *(const float4*)(&Bs[buf][k][col0]);
            *(float4*)(b + 4) = *(const float4*)(&Bs[buf][k][col0 + 4]);
            #pragma unroll
            for (int i = 0; i < 8; i++)
                #pragma unroll
                for (int j = 0; j < 8; j++)
                    acc[i][j] = fmaf(a[i], b[j], acc[i][j]);
        }
        buf ^= 1;
    }

    // epilogue: bias + store (float4)
    float bv[8];
    *(float4*)(bv)     = *(const float4*)(bias + n0 + col0);
    *(float4*)(bv + 4) = *(const float4*)(bias + n0 + col0 + 4);
    #pragma unroll
    for (int i = 0; i < 8; i++) {
        float* Crow = C + (long)(m0 + row0 + i) * N + n0 + col0;
        float4 o0, o1;
        o0.x = acc[i][0] + bv[0]; o0.y = acc[i][1] + bv[1];
        o0.z = acc[i][2] + bv[2]; o0.w = acc[i][3] + bv[3];
        o1.x = acc[i][4] + bv[4]; o1.y = acc[i][5] + bv[5];
        o1.z = acc[i][6] + bv[6]; o1.w = acc[i][7] + bv[7];
        *(float4*)(Crow)     = o0;
        *(float4*)(Crow + 4) = o1;
    }
}

// ---------------------------------------------------------------------------
// Flash attention, fp32. One CTA per (b, h, 64-row q tile).
// Q/K/V layout: [B*S, D] row-major; head h occupies cols [h*64, h*64+64).
// BQ=BK=64, 256 threads: thread (tr,tc) owns 4x4 of every 64x64 tile.
// Smem (dynamic): Qs[64][76], KVs[64][76], Ps[64][76]  (~57 KB)
// ---------------------------------------------------------------------------
#define AP 76   // padded row stride (floats); 76*4=304B is 16B aligned, conflict-free

__global__ __launch_bounds__(256, 1)
void attn_kernel(const float* __restrict__ Q, const float* __restrict__ K,
                 const float* __restrict__ V, float* __restrict__ O)
{
    extern __shared__ float sm[];
    float* Qs  = sm;             // [64][AP]
    float* KVs = sm + 64 * AP;   // [64][AP]
    float* Ps  = sm + 128 * AP;  // [64][AP]

    const int b  = blockIdx.z;
    const int h  = blockIdx.y;
    const int q0 = blockIdx.x * 64;
    const int tid = threadIdx.x;
    const int tc = tid & 15;     // col group (4 cols)
    const int tr = tid >> 4;     // row group (4 rows)

    const float* Qg = Q + ((long)b * SS + q0) * DD + h * HD;
    const float* Kg = K + (long)b * SS * DD + h * HD;
    const float* Vg = V + (long)b * SS * DD + h * HD;

    // load Q tile (64 rows x 64 cols) as float4s
    for (int i = tid; i < 64 * 16; i += 256) {
        int r = i >> 4, c4 = (i & 15) * 4;
        *(float4*)(Qs + r * AP + c4) = *(const float4*)(Qg + (long)r * DD + c4);
    }

    float acc[4][4];
    float mrow[4], lrow[4];
    #pragma unroll
    for (int i = 0; i < 4; i++) {
        mrow[i] = -1e30f; lrow[i] = 0.f;
        #pragma unroll
        for (int j = 0; j < 4; j++) acc[i][j] = 0.f;
    }
    __syncthreads();

    const float scale = 0.125f;   // 1/sqrt(64)

    for (int kt = 0; kt < SS / 64; kt++) {
        // ---- load K tile ----
        const float* Kt = Kg + (long)kt * 64 * DD;
        for (int i = tid; i < 64 * 16; i += 256) {
            int r = i >> 4, c4 = (i & 15) * 4;
            *(float4*)(KVs + r * AP + c4) = *(const float4*)(Kt + (long)r * DD + c4);
        }
        __syncthreads();

        // ---- S = Q @ K^T (64x64x64) ----
        float s[4][4];
        #pragma unroll
        for (int i = 0; i < 4; i++)
            #pragma unroll
            for (int j = 0; j < 4; j++) s[i][j] = 0.f;

        #pragma unroll
        for (int kk = 0; kk < HD; kk += 4) {
            float4 qv[4], kv[4];
            #pragma unroll
            for (int i = 0; i < 4; i++) qv[i] = *(const float4*)(Qs + (tr * 4 + i) * AP + kk);
            #pragma unroll
            for (int j = 0; j < 4; j++) kv[j] = *(const float4*)(KVs + (tc * 4 + j) * AP + kk);
            #pragma unroll
            for (int i = 0; i < 4; i++)
                #pragma unroll
                for (int j = 0; j < 4; j++) {
                    s[i][j] = fmaf(qv[i].x, kv[j].x, s[i][j]);
                    s[i][j] = fmaf(qv[i].y, kv[j].y, s[i][j]);
                    s[i][j] = fmaf(qv[i].z, kv[j].z, s[i][j]);
                    s[i][j] = fmaf(qv[i].w, kv[j].w, s[i][j]);
                }
        }

        // ---- online softmax (row reductions over 16-lane groups) ----
        float corr[4];
        #pragma unroll
        for (int i = 0; i < 4; i++) {
            float mx = fmaxf(fmaxf(s[i][0], s[i][1]), fmaxf(s[i][2], s[i][3]));
            #pragma unroll
            for (int off = 8; off >= 1; off >>= 1)
                mx = fmaxf(mx, __shfl_xor_sync(0xffffffffu, mx, off));
            mx *= scale;
            float mnew = fmaxf(mrow[i], mx);
            float sum = 0.f;
            #pragma unroll
            for (int j = 0; j < 4; j++) {
                float p = __expf(fmaf(s[i][j], scale, -mnew));
                s[i][j] = p;
                sum += p;
            }
            #pragma unroll
            for (int off = 8; off >= 1; off >>= 1)
                sum += __shfl_xor_sync(0xffffffffu, sum, off);
            corr[i] = __expf(mrow[i] - mnew);
            lrow[i] = lrow[i] * corr[i] + sum;
            mrow[i] = mnew;
        }
        #pragma unroll
        for (int i = 0; i < 4; i++) {
            #pragma unroll
            for (int j = 0; j < 4; j++) {
                acc[i][j] *= corr[i];
                Ps[(tr * 4 + i) * AP + tc * 4 + j] = s[i][j];
            }
        }
        __syncthreads();   // Ps written; all K reads done

        // ---- load V tile (reuse KVs) ----
        const float* Vt = Vg + (long)kt * 64 * DD;
        for (int i = tid; i < 64 * 16; i += 256) {
            int r = i >> 4, c4 = (i & 15) * 4;
            *(float4*)(KVs + r * AP + c4) = *(const float4*)(Vt + (long)r * DD + c4);
        }
        __syncthreads();

        // ---- acc += P @ V (64x64x64) ----
        #pragma unroll
        for (int kk = 0; kk < 64; kk += 4) {
            float4 pv[4];
            #pragma unroll
            for (int i = 0; i < 4; i++) pv[i] = *(const float4*)(Ps + (tr * 4 + i) * AP + kk);
            float vvf[4][4]; // [u][j]
            #pragma unroll
            for (int u = 0; u < 4; u++) {
                float4 t = *(const float4*)(KVs + (kk + u) * AP + tc * 4);
                vvf[u][0] = t.x; vvf[u][1] = t.y; vvf[u][2] = t.z; vvf[u][3] = t.w;
            }
            #pragma unroll
            for (int i = 0; i < 4; i++) {
                float pf[4] = { pv[i].x, pv[i].y, pv[i].z, pv[i].w };
                #pragma unroll
                for (int j = 0; j < 4; j++) {
                    #pragma unroll
                    for (int u = 0; u < 4; u++)
                        acc[i][j] = fmaf(pf[u], vvf[u][j], acc[i][j]);
                }
            }
        }
        __syncthreads();   // V (and Ps) reads done before next iter overwrites
    }

    // ---- epilogue: ctx = acc / l ----
    float* Og = O + ((long)b * SS + q0) * DD + h * HD;
    #pragma unroll
    for (int i = 0; i < 4; i++) {
        float inv = 1.f / lrow[i];
        float4 o;
        o.x = acc[i][0] * inv; o.y = acc[i][1] * inv;
        o.z = acc[i][2] * inv; o.w = acc[i][3] * inv;
        *(float4*)(Og + (long)(tr * 4 + i) * DD + tc * 4) = o;
    }
}

// ---------------------------------------------------------------------------
// Launch
// ---------------------------------------------------------------------------
extern "C" void kernel_launch(void* const* d_in, const int* in_sizes, int n_in,
                              void* d_out, int out_size)
{
    const float* query = (const float*)d_in[0];
    const float* key_  = (const float*)d_in[1];
    const float* value = (const float*)d_in[2];
    const float* wq    = (const float*)d_in[3];
    const float* bq    = (const float*)d_in[4];
    const float* wk    = (const float*)d_in[5];
    const float* bk    = (const float*)d_in[6];
    const float* wv    = (const float*)d_in[7];
    const float* bv    = (const float*)d_in[8];
    const float* wo    = (const float*)d_in[9];
    const float* bo    = (const float*)d_in[10];
    float* out = (float*)d_out;

    float *Qp, *Kp, *Vp, *Cp;
    cudaGetSymbolAddress((void**)&Qp, g_Q);
    cudaGetSymbolAddress((void**)&Kp, g_K);
    cudaGetSymbolAddress((void**)&Vp, g_V);
    cudaGetSymbolAddress((void**)&Cp, g_CTX);

    // opt-in to >48KB dynamic smem for attention (idempotent)
    const int attn_smem = 3 * 64 * AP * (int)sizeof(float);
    cudaFuncSetAttribute(attn_kernel, cudaFuncAttributeMaxDynamicSharedMemorySize, attn_smem);

    dim3 gblk(256), ggrid(DD / 128, MM / 128);

    sgemm_bias_kernel<<<ggrid, gblk>>>(query, wq, bq, Qp, MM, DD, DD);
    sgemm_bias_kernel<<<ggrid, gblk>>>(key_,  wk, bk, Kp, MM, DD, DD);
    sgemm_bias_kernel<<<ggrid, gblk>>>(value, wv, bv, Vp, MM, DD, DD);

    dim3 agrid(SS / 64, HH, BB);
    attn_kernel<<<agrid, 256, attn_smem>>>(Qp, Kp, Vp, Cp);

    sgemm_bias_kernel<<<ggrid, gblk>>>(Cp, wo, bo, out, MM, DD, DD);
}

// round 2
// speedup vs baseline: 3.5304x; 3.5304x over previous
#include <cuda_runtime.h>
#include <cuda_bf16.h>

typedef unsigned short u16;
typedef unsigned int   u32;

#define BB   4
#define SS   2048
#define DD   1024
#define HH   16
#define HD   64
#define MM   (BB*SS)

// ---------------------------------------------------------------------------
// Scratch: split-bf16 (hi/lo) buffers. ~164 MB total, allocation-free.
// ---------------------------------------------------------------------------
__device__ __align__(16) u16 g_Qhi[MM*DD], g_Qlo[MM*DD];
__device__ __align__(16) u16 g_Khi[MM*DD], g_Klo[MM*DD];
__device__ __align__(16) u16 g_Vhi[MM*DD], g_Vlo[MM*DD];
__device__ __align__(16) u16 g_Chi[MM*DD], g_Clo[MM*DD];
__device__ __align__(16) u16 g_Xhi[MM*DD], g_Xlo[MM*DD];
__device__ __align__(16) u16 g_Whi[DD*DD], g_Wlo[DD*DD];

// ---------------------------------------------------------------------------
// Helpers
// ---------------------------------------------------------------------------
__device__ __forceinline__ void split1(float v, u16& h, u16& l) {
    __nv_bfloat16 bh = __float2bfloat16_rn(v);
    h = __bfloat16_as_ushort(bh);
    __nv_bfloat16 bl = __float2bfloat16_rn(v - __bfloat162float(bh));
    l = __bfloat16_as_ushort(bl);
}

// pack two fp32 into (hi-pair, lo-pair) bf16x2 registers; low 16 bits = first elem
__device__ __forceinline__ void pack2(float x, float y, u32& h, u32& l) {
    u16 hx, lx, hy, ly;
    split1(x, hx, lx);
    split1(y, hy, ly);
    h = (u32)hx | ((u32)hy << 16);
    l = (u32)lx | ((u32)ly << 16);
}

__device__ __forceinline__ u32 smaddr(const void* p) {
    return (u32)__cvta_generic_to_shared(p);
}

__device__ __forceinline__ void ldmx4(u32 r[4], u32 addr) {
    asm volatile("ldmatrix.sync.aligned.m8n8.x4.shared.b16 {%0,%1,%2,%3}, [%4];"
                 : "=r"(r[0]), "=r"(r[1]), "=r"(r[2]), "=r"(r[3]) : "r"(addr));
}
__device__ __forceinline__ void ldmx4t(u32 r[4], u32 addr) {
    asm volatile("ldmatrix.sync.aligned.m8n8.x4.trans.shared.b16 {%0,%1,%2,%3}, [%4];"
                 : "=r"(r[0]), "=r"(r[1]), "=r"(r[2]), "=r"(r[3]) : "r"(addr));
}

__device__ __forceinline__ void mma16816(float c[4], const u32 a[4], const u32 b[2]) {
    asm volatile(
        "mma.sync.aligned.m16n8k16.row.col.f32.bf16.bf16.f32 "
        "{%0,%1,%2,%3},{%4,%5,%6,%7},{%8,%9},{%0,%1,%2,%3};"
        : "+f"(c[0]), "+f"(c[1]), "+f"(c[2]), "+f"(c[3])
        : "r"(a[0]), "r"(a[1]), "r"(a[2]), "r"(a[3]), "r"(b[0]), "r"(b[1]));
}

// ---------------------------------------------------------------------------
// Split conversion: fp32 -> (hi, lo) bf16, vectorized x4
// ---------------------------------------------------------------------------
__global__ void split_kernel(const float4* __restrict__ x,
                             ushort4* __restrict__ hi, ushort4* __restrict__ lo, int n4)
{
    int i = blockIdx.x * blockDim.x + threadIdx.x;
    if (i >= n4) return;
    float4 v = x[i];
    ushort4 h, l;
    split1(v.x, h.x, l.x);
    split1(v.y, h.y, l.y);
    split1(v.z, h.z, l.z);
    split1(v.w, h.w, l.w);
    hi[i] = h;
    lo[i] = l;
}

// ---------------------------------------------------------------------------
// Split-bf16 GEMM: C[M,N] = (Ahi+Alo)[M,K] @ (Bhi+Blo)[K,N] + bias
// 128x128 tile, BK=32, 256 threads (8 warps, 2x4 -> 64x32 warp tiles).
// A row-major [M,K], B row-major [K,N].  splitOut: 0 -> fp32 Cf; 1 -> Chi/Clo.
// ---------------------------------------------------------------------------
#define GAP 40    // A smem row stride (bf16)
#define GBP 136   // B smem row stride (bf16)

__global__ __launch_bounds__(256)
void gemm_split_kernel(const u16* __restrict__ Ahi, const u16* __restrict__ Alo,
                       const u16* __restrict__ Bhi, const u16* __restrict__ Blo,
                       const float* __restrict__ bias,
                       float* __restrict__ Cf, u16* __restrict__ Chi, u16* __restrict__ Clo,
                       int M, int N, int K, int splitOut)
{
    __shared__ u16 sAh[128*GAP], sAl[128*GAP];
    __shared__ u16 sBh[32*GBP],  sBl[32*GBP];

    const int tid  = threadIdx.x;
    const int lane = tid & 31;
    const int warp = tid >> 5;
    const int wm = (warp >> 2) * 64;   // 0 / 64
    const int wn = (warp & 3) * 32;    // 0/32/64/96
    const int m0 = blockIdx.y * 128;
    const int n0 = blockIdx.x * 128;

    float acc[4][4][4];
    #pragma unroll
    for (int i = 0; i < 4; i++)
        #pragma unroll
        for (int j = 0; j < 4; j++)
            #pragma unroll
            for (int k = 0; k < 4; k++) acc[i][j][k] = 0.f;

    const int ar = tid >> 2;           // 0..63
    const int ac = (tid & 3) * 8;      // 0..24
    const int br = tid >> 4;           // 0..15
    const int bc = (tid & 15) * 8;     // 0..120

    for (int kt = 0; kt < K; kt += 32) {
        #pragma unroll
        for (int rep = 0; rep < 2; rep++) {
            int r = ar + rep * 64;
            size_t go = (size_t)(m0 + r) * K + kt + ac;
            *(uint4*)&sAh[r*GAP + ac] = *(const uint4*)&Ahi[go];
            *(uint4*)&sAl[r*GAP + ac] = *(const uint4*)&Alo[go];
        }
        #pragma unroll
        for (int rep = 0; rep < 2; rep++) {
            int r = br + rep * 16;
            size_t go = (size_t)(kt + r) * N + n0 + bc;
            *(uint4*)&sBh[r*GBP + bc] = *(const uint4*)&Bhi[go];
            *(uint4*)&sBl[r*GBP + bc] = *(const uint4*)&Blo[go];
        }
        __syncthreads();

        #pragma unroll
        for (int ks = 0; ks < 2; ks++) {
            const int k0 = ks * 16;
            // A fragments (row-major): row = m + lane%16, col = k0 + 8*(lane/16)
            u32 ah[4][4], al[4][4];
            #pragma unroll
            for (int mt = 0; mt < 4; mt++) {
                int row = wm + mt*16 + (lane & 15);
                int col = k0 + 8*(lane >> 4);
                ldmx4(ah[mt], smaddr(&sAh[row*GAP + col]));
                ldmx4(al[mt], smaddr(&sAl[row*GAP + col]));
            }
            // B fragments (row-major [K,N] -> trans): row = k0 + lane%16, col = n + 8*(lane/16)
            #pragma unroll
            for (int nt2 = 0; nt2 < 2; nt2++) {
                int brow = k0 + (lane & 15);
                int bcol = wn + nt2*16 + 8*(lane >> 4);
                u32 bh[4], bl[4];
                ldmx4t(bh, smaddr(&sBh[brow*GBP + bcol]));
                ldmx4t(bl, smaddr(&sBl[brow*GBP + bcol]));
                #pragma unroll
                for (int mt = 0; mt < 4; mt++) {
                    mma16816(acc[mt][nt2*2],   ah[mt], &bh[0]);
                    mma16816(acc[mt][nt2*2],   ah[mt], &bl[0]);
                    mma16816(acc[mt][nt2*2],   al[mt], &bh[0]);
                    mma16816(acc[mt][nt2*2+1], ah[mt], &bh[2]);
                    mma16816(acc[mt][nt2*2+1], ah[mt], &bl[2]);
                    mma16816(acc[mt][nt2*2+1], al[mt], &bh[2]);
                }
            }
        }
        __syncthreads();
    }

    // epilogue
    const int g = lane >> 2;
    #pragma unroll
    for (int mt = 0; mt < 4; mt++) {
        int r0 = m0 + wm + mt*16 + g;
        #pragma unroll
        for (int nt = 0; nt < 4; nt++) {
            int c = n0 + wn + nt*8 + (lane & 3)*2;
            float b0 = bias[c], b1 = bias[c+1];
            float v0 = acc[mt][nt][0] + b0, v1 = acc[mt][nt][1] + b1;
            float v2 = acc[mt][nt][2] + b0, v3 = acc[mt][nt][3] + b1;
            if (!splitOut) {
                *(float2*)&Cf[(size_t)r0*N + c]     = make_float2(v0, v1);
                *(float2*)&Cf[(size_t)(r0+8)*N + c] = make_float2(v2, v3);
            } else {
                u32 h, l;
                pack2(v0, v1, h, l);
                *(u32*)&Chi[(size_t)r0*N + c] = h;
                *(u32*)&Clo[(size_t)r0*N + c] = l;
                pack2(v2, v3, h, l);
                *(u32*)&Chi[(size_t)(r0+8)*N + c] = h;
                *(u32*)&Clo[(size_t)(r0+8)*N + c] = l;
            }
        }
    }
}

// ---------------------------------------------------------------------------
// Flash attention, split-bf16 mma. CTA = (b, h, 64-q-rows), 128 threads (4 warps).
// Each warp: 16 q-rows. BK=64. S and PV both via 3-MMA split scheme.
// ---------------------------------------------------------------------------
#define AQP 72    // smem row stride (bf16)
#define ATTN_SMEM (6 * 64 * AQP * 2)

__global__ __launch_bounds__(128)
void attn_mma_kernel(const u16* __restrict__ Qhi, const u16* __restrict__ Qlo,
                     const u16* __restrict__ Khi, const u16* __restrict__ Klo,
                     const u16* __restrict__ Vhi, const u16* __restrict__ Vlo,
                     u16* __restrict__ Chi, u16* __restrict__ Clo)
{
    extern __shared__ u16 sm[];
    u16* sQh = sm;
    u16* sQl = sQh + 64*AQP;
    u16* sKh = sQl + 64*AQP;
    u16* sKl = sKh + 64*AQP;
    u16* sVh = sKl + 64*AQP;
    u16* sVl = sVh + 64*AQP;

    const int b = blockIdx.z, h = blockIdx.y, q0 = blockIdx.x * 64;
    const int tid = threadIdx.x, lane = tid & 31, warp = tid >> 5;
    const int g = lane >> 2;

    const size_t headoff = (size_t)h * HD;
    const u16* Qgh = Qhi + ((size_t)b*SS + q0)*DD + headoff;
    const u16* Qgl = Qlo + ((size_t)b*SS + q0)*DD + headoff;
    const u16* Kgh = Khi + (size_t)b*SS*DD + headoff;
    const u16* Kgl = Klo + (size_t)b*SS*DD + headoff;
    const u16* Vgh = Vhi + (size_t)b*SS*DD + headoff;
    const u16* Vgl = Vlo + (size_t)b*SS*DD + headoff;

    // Q tile 64x64
    for (int i = tid; i < 512; i += 128) {
        int r = i >> 3, c8 = (i & 7) * 8;
        size_t go = (size_t)r*DD + c8;
        *(uint4*)&sQh[r*AQP + c8] = *(const uint4*)&Qgh[go];
        *(uint4*)&sQl[r*AQP + c8] = *(const uint4*)&Qgl[go];
    }

    float o[8][4];
    #pragma unroll
    for (int i = 0; i < 8; i++)
        #pragma unroll
        for (int j = 0; j < 4; j++) o[i][j] = 0.f;
    float mrow0 = -1e30f, mrow1 = -1e30f, lrow0 = 0.f, lrow1 = 0.f;
    const float scale = 0.125f;   // 1/sqrt(64)

    for (int kt = 0; kt < SS; kt += 64) {
        __syncthreads();   // previous compute done (also covers Q-tile stores)
        for (int i = tid; i < 512; i += 128) {
            int r = i >> 3, c8 = (i & 7) * 8;
            size_t go = (size_t)(kt + r)*DD + c8;
            *(uint4*)&sKh[r*AQP + c8] = *(const uint4*)&Kgh[go];
            *(uint4*)&sKl[r*AQP + c8] = *(const uint4*)&Kgl[go];
            *(uint4*)&sVh[r*AQP + c8] = *(const uint4*)&Vgh[go];
            *(uint4*)&sVl[r*AQP + c8] = *(const uint4*)&Vgl[go];
        }
        __syncthreads();

        // ---- S = Q K^T (16 x 64 per warp) ----
        float s[8][4];
        #pragma unroll
        for (int i = 0; i < 8; i++)
            #pragma unroll
            for (int j = 0; j < 4; j++) s[i][j] = 0.f;

        #pragma unroll
        for (int k0 = 0; k0 < 64; k0 += 16) {
            u32 qh[4], ql[4];
            {
                int row = warp*16 + (lane & 15);
                int col = k0 + 8*(lane >> 4);
                ldmx4(qh, smaddr(&sQh[row*AQP + col]));
                ldmx4(ql, smaddr(&sQl[row*AQP + col]));
            }
            #pragma unroll
            for (int nt2 = 0; nt2 < 4; nt2++) {
                // K row-major [n][k] -> B frag via non-trans ldmatrix
                int krow = nt2*16 + (lane & 7) + 8*(lane >> 4);
                int kcol = k0 + 8*((lane >> 3) & 1);
                u32 kh[4], kl[4];
                ldmx4(kh, smaddr(&sKh[krow*AQP + kcol]));
                ldmx4(kl, smaddr(&sKl[krow*AQP + kcol]));
                mma16816(s[nt2*2],   qh, &kh[0]);
                mma16816(s[nt2*2],   qh, &kl[0]);
                mma16816(s[nt2*2],   ql, &kh[0]);
                mma16816(s[nt2*2+1], qh, &kh[2]);
                mma16816(s[nt2*2+1], qh, &kl[2]);
                mma16816(s[nt2*2+1], ql, &kh[2]);
            }
        }

        // ---- online softmax; thread owns rows g (c0,c1) and g+8 (c2,c3) ----
        float mx0 = -1e30f, mx1 = -1e30f;
        #pragma unroll
        for (int nt = 0; nt < 8; nt++) {
            mx0 = fmaxf(mx0, fmaxf(s[nt][0], s[nt][1]));
            mx1 = fmaxf(mx1, fmaxf(s[nt][2], s[nt][3]));
        }
        mx0 = fmaxf(mx0, __shfl_xor_sync(0xffffffffu, mx0, 1));
        mx0 = fmaxf(mx0, __shfl_xor_sync(0xffffffffu, mx0, 2));
        mx1 = fmaxf(mx1, __shfl_xor_sync(0xffffffffu, mx1, 1));
        mx1 = fmaxf(mx1, __shfl_xor_sync(0xffffffffu, mx1, 2));
        float mn0 = fmaxf(mrow0, mx0*scale);
        float mn1 = fmaxf(mrow1, mx1*scale);
        float sum0 = 0.f, sum1 = 0.f;
        #pragma unroll
        for (int nt = 0; nt < 8; nt++) {
            s[nt][0] = __expf(fmaf(s[nt][0], scale, -mn0)); sum0 += s[nt][0];
            s[nt][1] = __expf(fmaf(s[nt][1], scale, -mn0)); sum0 += s[nt][1];
            s[nt][2] = __expf(fmaf(s[nt][2], scale, -mn1)); sum1 += s[nt][2];
            s[nt][3] = __expf(fmaf(s[nt][3], scale, -mn1)); sum1 += s[nt][3];
        }
        sum0 += __shfl_xor_sync(0xffffffffu, sum0, 1);
        sum0 += __shfl_xor_sync(0xffffffffu, sum0, 2);
        sum1 += __shfl_xor_sync(0xffffffffu, sum1, 1);
        sum1 += __shfl_xor_sync(0xffffffffu, sum1, 2);
        float c0 = __expf(mrow0 - mn0), c1 = __expf(mrow1 - mn1);
        lrow0 = lrow0*c0 + sum0;  mrow0 = mn0;
        lrow1 = lrow1*c1 + sum1;  mrow1 = mn1;
        #pragma unroll
        for (int nt = 0; nt < 8; nt++) {
            o[nt][0] *= c0; o[nt][1] *= c0;
            o[nt][2] *= c1; o[nt][3] *= c1;
        }

        // ---- O += P V ----
        #pragma unroll
        for (int j = 0; j < 4; j++) {          // PV k-step: uses S n-tiles 2j, 2j+1
            u32 ph[4], pl[4];
            pack2(s[2*j][0],   s[2*j][1],   ph[0], pl[0]);
            pack2(s[2*j][2],   s[2*j][3],   ph[1], pl[1]);
            pack2(s[2*j+1][0], s[2*j+1][1], ph[2], pl[2]);
            pack2(s[2*j+1][2], s[2*j+1][3], ph[3], pl[3]);
            int vrow = j*16 + (lane & 15);
            #pragma unroll
            for (int nt2 = 0; nt2 < 4; nt2++) {
                int vcol = nt2*16 + 8*(lane >> 4);
                u32 vh[4], vl[4];
                ldmx4t(vh, smaddr(&sVh[vrow*AQP + vcol]));
                ldmx4t(vl, smaddr(&sVl[vrow*AQP + vcol]));
                mma16816(o[nt2*2],   ph, &vh[0]);
                mma16816(o[nt2*2],   ph, &vl[0]);
                mma16816(o[nt2*2],   pl, &vh[0]);
                mma16816(o[nt2*2+1], ph, &vh[2]);
                mma16816(o[nt2*2+1], ph, &vl[2]);
                mma16816(o[nt2*2+1], pl, &vh[2]);
            }
        }
    }

    // ---- epilogue: ctx = o / l, split-store bf16 hi/lo ----
    float inv0 = 1.f / lrow0, inv1 = 1.f / lrow1;
    size_t r0 = (size_t)b*SS + q0 + warp*16 + g;
    #pragma unroll
    for (int nt = 0; nt < 8; nt++) {
        int c = (int)headoff + nt*8 + (lane & 3)*2;
        u32 hbits, lbits;
        pack2(o[nt][0]*inv0, o[nt][1]*inv0, hbits, lbits);
        *(u32*)&Chi[r0*DD + c] = hbits;
        *(u32*)&Clo[r0*DD + c] = lbits;
        pack2(o[nt][2]*inv1, o[nt][3]*inv1, hbits, lbits);
        *(u32*)&Chi[(r0+8)*DD + c] = hbits;
        *(u32*)&Clo[(r0+8)*DD + c] = lbits;
    }
}

// ---------------------------------------------------------------------------
// Launch
// ---------------------------------------------------------------------------
extern "C" void kernel_launch(void* const* d_in, const int* in_sizes, int n_in,
                              void* d_out, int out_size)
{
    const float* query = (const float*)d_in[0];
    const float* key_  = (const float*)d_in[1];
    const float* value = (const float*)d_in[2];
    const float* wq    = (const float*)d_in[3];
    const float* bq    = (const float*)d_in[4];
    const float* wk    = (const float*)d_in[5];
    const float* bk    = (const float*)d_in[6];
    const float* wv    = (const float*)d_in[7];
    const float* bv    = (const float*)d_in[8];
    const float* wo    = (const float*)d_in[9];
    const float* bo    = (const float*)d_in[10];
    float* out = (float*)d_out;

    u16 *Qhi, *Qlo, *Khi, *Klo, *Vhi, *Vlo, *Chi, *Clo, *Xhi, *Xlo, *Whi, *Wlo;
    cudaGetSymbolAddress((void**)&Qhi, g_Qhi); cudaGetSymbolAddress((void**)&Qlo, g_Qlo);
    cudaGetSymbolAddress((void**)&Khi, g_Khi); cudaGetSymbolAddress((void**)&Klo, g_Klo);
    cudaGetSymbolAddress((void**)&Vhi, g_Vhi); cudaGetSymbolAddress((void**)&Vlo, g_Vlo);
    cudaGetSymbolAddress((void**)&Chi, g_Chi); cudaGetSymbolAddress((void**)&Clo, g_Clo);
    cudaGetSymbolAddress((void**)&Xhi, g_Xhi); cudaGetSymbolAddress((void**)&Xlo, g_Xlo);
    cudaGetSymbolAddress((void**)&Whi, g_Whi); cudaGetSymbolAddress((void**)&Wlo, g_Wlo);

    cudaFuncSetAttribute(attn_mma_kernel, cudaFuncAttributeMaxDynamicSharedMemorySize, ATTN_SMEM);

    const int nX4 = MM*DD/4, nW4 = DD*DD/4;
    dim3 ggrid(DD/128, MM/128), gblk(256);

    // Q projection
    split_kernel<<<nX4/256, 256>>>((const float4*)query, (ushort4*)Xhi, (ushort4*)Xlo, nX4);
    split_kernel<<<nW4/256, 256>>>((const float4*)wq, (ushort4*)Whi, (ushort4*)Wlo, nW4);
    gemm_split_kernel<<<ggrid, gblk>>>(Xhi, Xlo, Whi, Wlo, bq, nullptr, Qhi, Qlo, MM, DD, DD, 1);
    // K projection
    split_kernel<<<nX4/256, 256>>>((const float4*)key_, (ushort4*)Xhi, (ushort4*)Xlo, nX4);
    split_kernel<<<nW4/256, 256>>>((const float4*)wk, (ushort4*)Whi, (ushort4*)Wlo, nW4);
    gemm_split_kernel<<<ggrid, gblk>>>(Xhi, Xlo, Whi, Wlo, bk, nullptr, Khi, Klo, MM, DD, DD, 1);
    // V projection
    split_kernel<<<nX4/256, 256>>>((const float4*)value, (ushort4*)Xhi, (ushort4*)Xlo, nX4);
    split_kernel<<<nW4/256, 256>>>((const float4*)wv, (ushort4*)Whi, (ushort4*)Wlo, nW4);
    gemm_split_kernel<<<ggrid, gblk>>>(Xhi, Xlo, Whi, Wlo, bv, nullptr, Vhi, Vlo, MM, DD, DD, 1);

    // attention
    dim3 agrid(SS/64, HH, BB);
    attn_mma_kernel<<<agrid, 128, ATTN_SMEM>>>(Qhi, Qlo, Khi, Klo, Vhi, Vlo, Chi, Clo);

    // O projection (fp32 out)
    split_kernel<<<nW4/256, 256>>>((const float4*)wo, (ushort4*)Whi, (ushort4*)Wlo, nW4);
    gemm_split_kernel<<<ggrid, gblk>>>(Chi, Clo, Whi, Wlo, bo, out, nullptr, nullptr, MM, DD, DD, 0);
}